// round 2
// baseline (speedup 1.0000x reference)
#include <cuda_runtime.h>

// PixelWiseNet: out[h,w] = bias + sum_c sum_k p_a[c,k] * relu(x[c,h,w]*rowsum(M[c]) + bias_c[c] - p_t[c,k])
// C=3, H=W=1024, K=16.
//
// Inputs (metadata order): x [3,1024,1024] f32, M [3,3] f32, p_a [3,16] f32,
// p_t [3,16] f32, bias_c [3] f32, bias [1] f32. Output [1024,1024] f32.

#define C 3
#define K 16
#define HW (1024 * 1024)
#define N4 (HW / 4)          // float4 elements per channel plane
#define THREADS 256
#define BLOCKS (N4 / THREADS)  // 1024

__global__ __launch_bounds__(THREADS)
void pixelwise_kernel(const float4* __restrict__ x,
                      const float* __restrict__ M,
                      const float* __restrict__ p_a,
                      const float* __restrict__ p_t,
                      const float* __restrict__ bias_c,
                      const float* __restrict__ bias,
                      float4* __restrict__ out) {
    // Shared param staging: scale[3], bc[3], pa[48], pt[48], bias
    __shared__ float sh_scale[C];
    __shared__ float sh_bc[C];
    __shared__ float sh_pa[C * K];
    __shared__ float sh_pt[C * K];
    __shared__ float sh_bias;

    int tid = threadIdx.x;
    if (tid < C) {
        sh_scale[tid] = M[tid * 3 + 0] + M[tid * 3 + 1] + M[tid * 3 + 2];
        sh_bc[tid] = bias_c[tid];
    }
    if (tid < C * K) {
        sh_pa[tid] = p_a[tid];
        sh_pt[tid] = p_t[tid];
    }
    if (tid == 0) sh_bias = bias[0];
    __syncthreads();

    int i = blockIdx.x * THREADS + tid;

    float b = sh_bias;
    float4 acc = make_float4(b, b, b, b);

#pragma unroll
    for (int c = 0; c < C; c++) {
        float4 xv = x[c * N4 + i];
        float scale = sh_scale[c];
        float bc = sh_bc[c];
        float sx = fmaf(xv.x, scale, bc);
        float sy = fmaf(xv.y, scale, bc);
        float sz = fmaf(xv.z, scale, bc);
        float sw = fmaf(xv.w, scale, bc);
#pragma unroll
        for (int k = 0; k < K; k++) {
            float a = sh_pa[c * K + k];
            float t = sh_pt[c * K + k];
            acc.x = fmaf(a, fmaxf(sx - t, 0.0f), acc.x);
            acc.y = fmaf(a, fmaxf(sy - t, 0.0f), acc.y);
            acc.z = fmaf(a, fmaxf(sz - t, 0.0f), acc.z);
            acc.w = fmaf(a, fmaxf(sw - t, 0.0f), acc.w);
        }
    }

    out[i] = acc;
}

extern "C" void kernel_launch(void* const* d_in, const int* in_sizes, int n_in,
                              void* d_out, int out_size) {
    const float4* x      = (const float4*)d_in[0];
    const float*  M      = (const float*)d_in[1];
    const float*  p_a    = (const float*)d_in[2];
    const float*  p_t    = (const float*)d_in[3];
    const float*  bias_c = (const float*)d_in[4];
    const float*  bias   = (const float*)d_in[5];
    float4* out = (float4*)d_out;

    pixelwise_kernel<<<BLOCKS, THREADS>>>(x, M, p_a, p_t, bias_c, bias, out);
}